// round 16
// baseline (speedup 1.0000x reference)
#include <cuda_runtime.h>
#include <cuda_fp16.h>
#include <cstdint>

#define Bb 2
#define Hh 16
#define Ss 2048
#define Dd 64
#define BH (Bb*Hh)

typedef unsigned long long ull;

// ---------------- global scratch ----------------
__device__ unsigned int g_maskbits[(size_t)Bb * Ss * Ss / 32];
#define TILE_U2 1024      // uint2 granules per 8KB chunk-plane
__device__ uint2 gK2[(size_t)BH * 32 * TILE_U2];   // 8 MB (fp16 pairs, j-paired layout)
__device__ uint2 gV2[(size_t)BH * 32 * TILE_U2];   // 8 MB

// ---------------- helpers ----------------
__device__ __forceinline__ uint32_t smem_u32(const void* p) {
    uint32_t a;
    asm("{ .reg .u64 t; cvta.to.shared.u64 t, %1; cvt.u32.u64 %0, t; }" : "=r"(a) : "l"(p));
    return a;
}
__device__ __forceinline__ uint32_t packf16(float s0, float s1) {
    uint32_t p;   // low = s0, high = s1
    asm("cvt.rn.f16x2.f32 %0, %1, %2;" : "=r"(p) : "f"(s1), "f"(s0));
    return p;
}
__device__ __forceinline__ uint32_t hmul2(uint32_t a, uint32_t b) {
    uint32_t r;
    asm("mul.f16x2 %0, %1, %2;" : "=r"(r) : "r"(a), "r"(b));
    return r;
}
__device__ __forceinline__ void mma16f(float4& d, uint32_t a0, uint32_t a1, uint32_t a2,
                                       uint32_t a3, uint32_t b0, uint32_t b1)
{
    asm volatile(
        "mma.sync.aligned.m16n8k16.row.col.f32.f16.f16.f32 "
        "{%0,%1,%2,%3}, {%4,%5,%6,%7}, {%8,%9}, {%0,%1,%2,%3};"
        : "+f"(d.x), "+f"(d.y), "+f"(d.z), "+f"(d.w)
        : "r"(a0), "r"(a1), "r"(a2), "r"(a3), "r"(b0), "r"(b1));
}
__device__ __forceinline__ float ex2m(float x) {
    float r;
    asm("ex2.approx.f32 %0, %1;" : "=f"(r) : "f"(x));
    return r;
}
#define SC2 0x30003000u                       // fp16x2 {0.125, 0.125} (exact)
#define KC  (0.125f * 1.4426950408889634f)    // SCALE * log2(e); 0.125 scaling exact

// paired-j granule position (uint2 units): [ks][jp][lane*2 + (j&1)]
__device__ __forceinline__ int pidx(int ks, int j, int g4t) {
    return (ks * 4 + (j >> 1)) * 64 + g4t * 2 + (j & 1);
}

// ---------------- fused prepass: mask bits + K split + V split ----------------
__global__ void prep_kernel(const int* __restrict__ masks,
                            const float* __restrict__ k,
                            const float* __restrict__ v)
{
    int bid = blockIdx.x;
    int tid = threadIdx.x;
    if (bid < 32768) {                       // mask bits
        int e = bid * 256 + tid;
        int val = masks[e] != 0;
        unsigned bal = __ballot_sync(0xFFFFFFFFu, val);
        if ((tid & 31) == 0) g_maskbits[e >> 5] = bal;
    } else if (bid < 36864) {                // K split
        int idx = (bid - 32768) * 256 + tid;  // BH*2048*16
        int gidx = idx & 15;
        int tglob = (idx >> 4) & 2047;
        int bh = idx >> 15;
        int ks = gidx >> 2, tig = gidx & 3;
        const float* kr = k + ((size_t)bh * Ss + tglob) * Dd + 16 * ks + 2 * tig;
        float2 p0 = *(const float2*)kr;
        float2 p1 = *(const float2*)(kr + 8);
        int kt = tglob >> 6;
        int tl = tglob & 63;
        int j = tl >> 3, g = tl & 7;
        gK2[((size_t)bh * 32 + kt) * TILE_U2 + pidx(ks, j, g * 4 + tig)] =
            make_uint2(packf16(p0.x, p0.y), packf16(p1.x, p1.y));
    } else {                                 // V split (transposed)
        int idx = (bid - 36864) * 256 + tid;  // BH*32*16*64
        int d  = idx & 63;
        int gidx = (idx >> 6) & 15;
        int kt = (idx >> 10) & 31;
        int bh = idx >> 15;
        int ks = gidx >> 2, tig = gidx & 3;
        int t0 = kt * 64 + 16 * ks + 2 * tig;
        const float* vb = v + (size_t)bh * Ss * Dd + d;
        float v0 = vb[(size_t)t0 * Dd];
        float v1 = vb[(size_t)(t0 + 1) * Dd];
        float v2 = vb[(size_t)(t0 + 8) * Dd];
        float v3 = vb[(size_t)(t0 + 9) * Dd];
        int j = d >> 3, g = d & 7;
        gV2[((size_t)bh * 32 + kt) * TILE_U2 + pidx(ks, j, g * 4 + tig)] =
            make_uint2(packf16(v0, v1), packf16(v2, v3));
    }
}

// ---------------- smem: 3-stage ring, stage = [K 8KB][V 8KB] ----------------
#define SINV 49152u
#define SMEM_TOTAL (49152 + 512)

__global__ void __launch_bounds__(256, 2)
sdpa_main_kernel(const float* __restrict__ q, float* __restrict__ out)
{
    extern __shared__ char smc[];
    const uint32_t sb = smem_u32(smc);
    float* sInv = (float*)(smc + SINV);

    const int tid  = threadIdx.x;
    const int lane = tid & 31;
    const int w    = tid >> 5;
    const int g    = lane >> 2;
    const int tig  = lane & 3;

    const int bh = blockIdx.y;
    const int b  = bh >> 4;
    const int s0 = blockIdx.x * 128;

    const float* qg = q + ((size_t)bh * Ss + s0) * Dd;
    float* outg = out + ((size_t)bh * Ss + s0) * Dd;
    float* attg = out + (size_t)BH * Ss * Dd + ((size_t)bh * Ss + s0) * Ss;

    const size_t tilebase = (size_t)bh * 32;

    auto issue = [&](int kt) {
        uint32_t dstb = sb + (uint32_t)(kt % 3) * 16384u;
        const char* srcK = (const char*)(gK2 + (tilebase + kt) * TILE_U2);
        const char* srcV = (const char*)(gV2 + (tilebase + kt) * TILE_U2);
        #pragma unroll
        for (int i = 0; i < 2; ++i) {
            int off = (tid + i * 256) * 16;
            asm volatile("cp.async.cg.shared.global [%0], [%1], 16;"
                         :: "r"(dstb + off), "l"(srcK + off));
        }
        #pragma unroll
        for (int i = 0; i < 2; ++i) {
            int off = (tid + i * 256) * 16;
            asm volatile("cp.async.cg.shared.global [%0], [%1], 16;"
                         :: "r"(dstb + 8192u + off), "l"(srcV + off));
        }
        asm volatile("cp.async.commit_group;");
    };

    issue(0);
    issue(1);

    // ---- Q fragments: fp16-rounded, direct gmem loads (one-time) ----
    const int r0 = w * 16 + g;
    uint2 qh[4][2];
    {
        const float* q0 = qg + (size_t)r0 * Dd;
        const float* q8 = qg + (size_t)(r0 + 8) * Dd;
        #pragma unroll
        for (int ks = 0; ks < 4; ++ks) {
            int c = 16 * ks + 2 * tig;
            #pragma unroll
            for (int half = 0; half < 2; ++half) {
                const float* qr = half ? q8 : q0;
                float2 p0 = *(const float2*)(qr + c);
                float2 p1 = *(const float2*)(qr + c + 8);
                qh[ks][half] = make_uint2(packf16(p0.x, p0.y), packf16(p1.x, p1.y));
            }
        }
    }

    const ull* m64 = (const ull*)g_maskbits;
    const size_t mrow0 = ((size_t)b * Ss + s0 + r0) * (Ss / 64);
    const size_t mrow1 = mrow0 + 8 * (Ss / 64);

    float rs0 = 0.f, rs1 = 0.f;
    float4 po[8];
    #pragma unroll
    for (int j = 0; j < 8; ++j) po[j] = make_float4(0.f, 0.f, 0.f, 0.f);

    float* att0 = attg + (size_t)r0 * Ss;
    float* att1 = attg + (size_t)(r0 + 8) * Ss;

    for (int kt = 0; kt < 32; ++kt) {
        if (kt < 31) { asm volatile("cp.async.wait_group 1;"); }
        else         { asm volatile("cp.async.wait_group 0;"); }
        __syncthreads();
        if (kt < 30) issue(kt + 2);

        const uint4* kb4 = (const uint4*)(smc + (kt % 3) * 16384);
        const uint4* vb4 = kb4 + 512;

        ull mw0 = m64[mrow0 + kt];
        ull mw1 = m64[mrow1 + kt];

        // ---- QK: one LDS.128 feeds 2 mma ----
        float4 cf[8];
        #pragma unroll
        for (int j = 0; j < 8; ++j) cf[j] = make_float4(0.f, 0.f, 0.f, 0.f);

        #pragma unroll
        for (int ks = 0; ks < 4; ++ks) {
            uint2 a0 = qh[ks][0], a8 = qh[ks][1];
            #pragma unroll
            for (int jp = 0; jp < 4; ++jp) {
                uint4 F = kb4[(ks * 4 + jp) * 32 + lane];
                mma16f(cf[2 * jp],     a0.x, a8.x, a0.y, a8.y, F.x, F.y);
                mma16f(cf[2 * jp + 1], a0.x, a8.x, a0.y, a8.y, F.z, F.w);
            }
        }

        // ---- lean epilogue (bit-identical outputs to rd12/rd15) fused with PV ----
        const int t0k = kt * 64;
        #pragma unroll
        for (int ks2 = 0; ks2 < 4; ++ks2) {
            uint32_t pah[2], pbh[2];
            #pragma unroll
            for (int u = 0; u < 2; ++u) {
                int j = 2 * ks2 + u;
                int c0 = 8 * j + 2 * tig;
                float4 c = cf[j];
                uint32_t t0 = (uint32_t)(mw0 >> c0) & 3u;
                uint32_t t1 = (uint32_t)(mw1 >> c0) & 3u;
                uint32_t mm0 = (t0 & 1u) * 0xFFFFu | (t0 >> 1) * 0xFFFF0000u;
                uint32_t mm1 = (t1 & 1u) * 0xFFFFu | (t1 >> 1) * 0xFFFF0000u;
                // fp16(c*0.125) == fp16(c)*0.125 (exact pow2); fp16(-1e-12) == -0 == masked +0
                pah[u] = hmul2(packf16(c.x, c.y), SC2) & mm0;
                pbh[u] = hmul2(packf16(c.z, c.w), SC2) & mm1;
                // ex2((c*0.125)*L2E) == ex2(c*KC) bit-exactly; masked -> exp(-1e-12) == 1.0f
                float e00 = (t0 & 1u) ? ex2m(c.x * KC) : 1.0f;
                float e01 = (t0 & 2u) ? ex2m(c.y * KC) : 1.0f;
                float e10 = (t1 & 1u) ? ex2m(c.z * KC) : 1.0f;
                float e11 = (t1 & 2u) ? ex2m(c.w * KC) : 1.0f;
                rs0 += e00 + e01; rs1 += e10 + e11;
                *(float2*)(att0 + t0k + c0) = make_float2(e00, e01);
                *(float2*)(att1 + t0k + c0) = make_float2(e10, e11);
            }
            #pragma unroll
            for (int jp = 0; jp < 4; ++jp) {
                uint4 F = vb4[(ks2 * 4 + jp) * 32 + lane];
                mma16f(po[2 * jp],     pah[0], pbh[0], pah[1], pbh[1], F.x, F.y);
                mma16f(po[2 * jp + 1], pah[0], pbh[0], pah[1], pbh[1], F.z, F.w);
            }
        }
        __syncthreads();   // all warps done with stage (kt%3) before refill
    }

    // ---- write output ----
    #pragma unroll
    for (int j = 0; j < 8; ++j) {
        int c0 = 8 * j + 2 * tig;
        *(float2*)(outg + (size_t)r0 * Dd + c0)       = make_float2(po[j].x, po[j].y);
        *(float2*)(outg + (size_t)(r0 + 8) * Dd + c0) = make_float2(po[j].z, po[j].w);
    }

    // ---- rowsum reduce ----
    rs0 += __shfl_xor_sync(0xFFFFFFFFu, rs0, 1);
    rs0 += __shfl_xor_sync(0xFFFFFFFFu, rs0, 2);
    rs1 += __shfl_xor_sync(0xFFFFFFFFu, rs1, 1);
    rs1 += __shfl_xor_sync(0xFFFFFFFFu, rs1, 2);
    if (tig == 0) {
        sInv[r0]     = 1.f / rs0;
        sInv[r0 + 8] = 1.f / rs1;
    }
    __syncthreads();

    // ---- normalize att in place (fp32) ----
    for (int r = 0; r < 128; ++r) {
        float iv = sInv[r];
        float* row = attg + (size_t)r * Ss + tid * 8;
        float4 a = *(const float4*)(row);
        float4 c = *(const float4*)(row + 4);
        a.x *= iv; a.y *= iv; a.z *= iv; a.w *= iv;
        c.x *= iv; c.y *= iv; c.z *= iv; c.w *= iv;
        *(float4*)(row)     = a;
        *(float4*)(row + 4) = c;
    }
}

extern "C" void kernel_launch(void* const* d_in, const int* in_sizes, int n_in,
                              void* d_out, int out_size)
{
    const float* q = (const float*)d_in[0];
    const float* k = (const float*)d_in[1];
    const float* v = (const float*)d_in[2];
    const int* masks = (const int*)d_in[3];
    float* out = (float*)d_out;

    prep_kernel<<<40960, 256>>>(masks, k, v);

    cudaFuncSetAttribute(sdpa_main_kernel,
                         cudaFuncAttributeMaxDynamicSharedMemorySize, SMEM_TOTAL);

    dim3 grid(Ss / 128, BH);   // (16, 32)
    sdpa_main_kernel<<<grid, 256, SMEM_TOTAL>>>(q, out);
}

// round 17
// speedup vs baseline: 1.1139x; 1.1139x over previous
#include <cuda_runtime.h>
#include <cuda_fp16.h>
#include <cstdint>

#define Bb 2
#define Hh 16
#define Ss 2048
#define Dd 64
#define BH (Bb*Hh)
#define SCALE 0.125f

typedef unsigned long long ull;

// ---------------- global scratch ----------------
__device__ unsigned int g_maskbits[(size_t)Bb * Ss * Ss / 32];
#define TILE_U2 1024      // uint2 granules per 8KB chunk-plane
__device__ uint2 gK2[(size_t)BH * 32 * TILE_U2];   // 8 MB (fp16 pairs, j-paired layout)
__device__ uint2 gV2[(size_t)BH * 32 * TILE_U2];   // 8 MB

// ---------------- helpers ----------------
__device__ __forceinline__ uint32_t smem_u32(const void* p) {
    uint32_t a;
    asm("{ .reg .u64 t; cvta.to.shared.u64 t, %1; cvt.u32.u64 %0, t; }" : "=r"(a) : "l"(p));
    return a;
}
__device__ __forceinline__ uint32_t packf16(float s0, float s1) {
    uint32_t p;   // low = s0, high = s1
    asm("cvt.rn.f16x2.f32 %0, %1, %2;" : "=r"(p) : "f"(s1), "f"(s0));
    return p;
}
__device__ __forceinline__ void mma16f(float4& d, uint32_t a0, uint32_t a1, uint32_t a2,
                                       uint32_t a3, uint32_t b0, uint32_t b1)
{
    asm volatile(
        "mma.sync.aligned.m16n8k16.row.col.f32.f16.f16.f32 "
        "{%0,%1,%2,%3}, {%4,%5,%6,%7}, {%8,%9}, {%0,%1,%2,%3};"
        : "+f"(d.x), "+f"(d.y), "+f"(d.z), "+f"(d.w)
        : "r"(a0), "r"(a1), "r"(a2), "r"(a3), "r"(b0), "r"(b1));
}
__device__ __forceinline__ float ex2m(float x) {
    float r;
    asm("ex2.approx.f32 %0, %1;" : "=f"(r) : "f"(x));
    return r;
}
#define L2E 1.4426950408889634f

// streaming (evict-first) global access helpers
__device__ __forceinline__ void stcs_f2(float* p, float a, float b) {
    asm volatile("st.global.cs.v2.f32 [%0], {%1, %2};" :: "l"(p), "f"(a), "f"(b) : "memory");
}
__device__ __forceinline__ float4 ldcs_f4(const float* p) {
    float4 r;
    asm volatile("ld.global.cs.v4.f32 {%0,%1,%2,%3}, [%4];"
                 : "=f"(r.x), "=f"(r.y), "=f"(r.z), "=f"(r.w) : "l"(p));
    return r;
}
__device__ __forceinline__ void stcs_f4(float* p, float4 v) {
    asm volatile("st.global.cs.v4.f32 [%0], {%1,%2,%3,%4};"
                 :: "l"(p), "f"(v.x), "f"(v.y), "f"(v.z), "f"(v.w) : "memory");
}

// paired-j granule position (uint2 units): [ks][jp][lane*2 + (j&1)]
__device__ __forceinline__ int pidx(int ks, int j, int g4t) {
    return (ks * 4 + (j >> 1)) * 64 + g4t * 2 + (j & 1);
}

// ---------------- fused prepass: mask bits + K split + V split ----------------
__global__ void prep_kernel(const int* __restrict__ masks,
                            const float* __restrict__ k,
                            const float* __restrict__ v)
{
    int bid = blockIdx.x;
    int tid = threadIdx.x;
    if (bid < 32768) {                       // mask bits
        int e = bid * 256 + tid;
        int val = masks[e] != 0;
        unsigned bal = __ballot_sync(0xFFFFFFFFu, val);
        if ((tid & 31) == 0) g_maskbits[e >> 5] = bal;
    } else if (bid < 36864) {                // K split
        int idx = (bid - 32768) * 256 + tid;  // BH*2048*16
        int gidx = idx & 15;
        int tglob = (idx >> 4) & 2047;
        int bh = idx >> 15;
        int ks = gidx >> 2, tig = gidx & 3;
        const float* kr = k + ((size_t)bh * Ss + tglob) * Dd + 16 * ks + 2 * tig;
        float2 p0 = *(const float2*)kr;
        float2 p1 = *(const float2*)(kr + 8);
        int kt = tglob >> 6;
        int tl = tglob & 63;
        int j = tl >> 3, g = tl & 7;
        gK2[((size_t)bh * 32 + kt) * TILE_U2 + pidx(ks, j, g * 4 + tig)] =
            make_uint2(packf16(p0.x, p0.y), packf16(p1.x, p1.y));
    } else {                                 // V split (transposed)
        int idx = (bid - 36864) * 256 + tid;  // BH*32*16*64
        int d  = idx & 63;
        int gidx = (idx >> 6) & 15;
        int kt = (idx >> 10) & 31;
        int bh = idx >> 15;
        int ks = gidx >> 2, tig = gidx & 3;
        int t0 = kt * 64 + 16 * ks + 2 * tig;
        const float* vb = v + (size_t)bh * Ss * Dd + d;
        float v0 = vb[(size_t)t0 * Dd];
        float v1 = vb[(size_t)(t0 + 1) * Dd];
        float v2 = vb[(size_t)(t0 + 8) * Dd];
        float v3 = vb[(size_t)(t0 + 9) * Dd];
        int j = d >> 3, g = d & 7;
        gV2[((size_t)bh * 32 + kt) * TILE_U2 + pidx(ks, j, g * 4 + tig)] =
            make_uint2(packf16(v0, v1), packf16(v2, v3));
    }
}

// ---------------- smem: 3-stage ring, stage = [K 8KB][V 8KB] ----------------
#define SINV 49152u
#define SMEM_TOTAL (49152 + 512)

__global__ void __launch_bounds__(256, 2)
sdpa_main_kernel(const float* __restrict__ q, float* __restrict__ out)
{
    extern __shared__ char smc[];
    const uint32_t sb = smem_u32(smc);
    float* sInv = (float*)(smc + SINV);

    const int tid  = threadIdx.x;
    const int lane = tid & 31;
    const int w    = tid >> 5;
    const int g    = lane >> 2;
    const int tig  = lane & 3;

    const int bh = blockIdx.y;
    const int b  = bh >> 4;
    const int s0 = blockIdx.x * 128;

    const float* qg = q + ((size_t)bh * Ss + s0) * Dd;
    float* outg = out + ((size_t)bh * Ss + s0) * Dd;
    float* attg = out + (size_t)BH * Ss * Dd + ((size_t)bh * Ss + s0) * Ss;

    const size_t tilebase = (size_t)bh * 32;

    auto issue = [&](int kt) {
        uint32_t dstb = sb + (uint32_t)(kt % 3) * 16384u;
        const char* srcK = (const char*)(gK2 + (tilebase + kt) * TILE_U2);
        const char* srcV = (const char*)(gV2 + (tilebase + kt) * TILE_U2);
        #pragma unroll
        for (int i = 0; i < 2; ++i) {
            int off = (tid + i * 256) * 16;
            asm volatile("cp.async.cg.shared.global [%0], [%1], 16;"
                         :: "r"(dstb + off), "l"(srcK + off));
        }
        #pragma unroll
        for (int i = 0; i < 2; ++i) {
            int off = (tid + i * 256) * 16;
            asm volatile("cp.async.cg.shared.global [%0], [%1], 16;"
                         :: "r"(dstb + 8192u + off), "l"(srcV + off));
        }
        asm volatile("cp.async.commit_group;");
    };

    issue(0);
    issue(1);

    // ---- Q fragments: fp16-rounded, direct gmem loads (one-time) ----
    const int r0 = w * 16 + g;
    uint2 qh[4][2];
    {
        const float* q0 = qg + (size_t)r0 * Dd;
        const float* q8 = qg + (size_t)(r0 + 8) * Dd;
        #pragma unroll
        for (int ks = 0; ks < 4; ++ks) {
            int c = 16 * ks + 2 * tig;
            #pragma unroll
            for (int half = 0; half < 2; ++half) {
                const float* qr = half ? q8 : q0;
                float2 p0 = *(const float2*)(qr + c);
                float2 p1 = *(const float2*)(qr + c + 8);
                qh[ks][half] = make_uint2(packf16(p0.x, p0.y), packf16(p1.x, p1.y));
            }
        }
    }

    const ull* m64 = (const ull*)g_maskbits;
    const size_t mrow0 = ((size_t)b * Ss + s0 + r0) * (Ss / 64);
    const size_t mrow1 = mrow0 + 8 * (Ss / 64);

    float rs0 = 0.f, rs1 = 0.f;
    float4 po[8];
    #pragma unroll
    for (int j = 0; j < 8; ++j) po[j] = make_float4(0.f, 0.f, 0.f, 0.f);

    float* att0 = attg + (size_t)r0 * Ss;
    float* att1 = attg + (size_t)(r0 + 8) * Ss;

    for (int kt = 0; kt < 32; ++kt) {
        if (kt < 31) { asm volatile("cp.async.wait_group 1;"); }
        else         { asm volatile("cp.async.wait_group 0;"); }
        __syncthreads();
        if (kt < 30) issue(kt + 2);

        const uint4* kb4 = (const uint4*)(smc + (kt % 3) * 16384);
        const uint4* vb4 = kb4 + 512;

        ull mw0 = m64[mrow0 + kt];
        ull mw1 = m64[mrow1 + kt];

        // ---- QK: one LDS.128 feeds 2 mma ----
        float4 cf[8];
        #pragma unroll
        for (int j = 0; j < 8; ++j) cf[j] = make_float4(0.f, 0.f, 0.f, 0.f);

        #pragma unroll
        for (int ks = 0; ks < 4; ++ks) {
            uint2 a0 = qh[ks][0], a8 = qh[ks][1];
            #pragma unroll
            for (int jp = 0; jp < 4; ++jp) {
                uint4 F = kb4[(ks * 4 + jp) * 32 + lane];
                mma16f(cf[2 * jp],     a0.x, a8.x, a0.y, a8.y, F.x, F.y);
                mma16f(cf[2 * jp + 1], a0.x, a8.x, a0.y, a8.y, F.z, F.w);
            }
        }

        // ---- fp32 epilogue (rd15-exact) fused with PV; att stores streamed ----
        const int t0k = kt * 64;
        #pragma unroll
        for (int ks2 = 0; ks2 < 4; ++ks2) {
            uint32_t pah[2], pbh[2];
            #pragma unroll
            for (int u = 0; u < 2; ++u) {
                int j = 2 * ks2 + u;
                int c0 = 8 * j + 2 * tig;
                float4 c = cf[j];
                float s00 = ((mw0 >> c0) & 1ull)       ? c.x * SCALE : -1e-12f;
                float s01 = ((mw0 >> (c0 + 1)) & 1ull) ? c.y * SCALE : -1e-12f;
                float s10 = ((mw1 >> c0) & 1ull)       ? c.z * SCALE : -1e-12f;
                float s11 = ((mw1 >> (c0 + 1)) & 1ull) ? c.w * SCALE : -1e-12f;
                float e00 = ex2m(s00 * L2E), e01 = ex2m(s01 * L2E);
                float e10 = ex2m(s10 * L2E), e11 = ex2m(s11 * L2E);
                rs0 += e00 + e01; rs1 += e10 + e11;
                stcs_f2(att0 + t0k + c0, e00, e01);
                stcs_f2(att1 + t0k + c0, e10, e11);
                pah[u] = packf16(s00, s01);
                pbh[u] = packf16(s10, s11);
            }
            #pragma unroll
            for (int jp = 0; jp < 4; ++jp) {
                uint4 F = vb4[(ks2 * 4 + jp) * 32 + lane];
                mma16f(po[2 * jp],     pah[0], pbh[0], pah[1], pbh[1], F.x, F.y);
                mma16f(po[2 * jp + 1], pah[0], pbh[0], pah[1], pbh[1], F.z, F.w);
            }
        }
        __syncthreads();   // all warps done with stage (kt%3) before refill
    }

    // ---- write output ----
    #pragma unroll
    for (int j = 0; j < 8; ++j) {
        int c0 = 8 * j + 2 * tig;
        *(float2*)(outg + (size_t)r0 * Dd + c0)       = make_float2(po[j].x, po[j].y);
        *(float2*)(outg + (size_t)(r0 + 8) * Dd + c0) = make_float2(po[j].z, po[j].w);
    }

    // ---- rowsum reduce ----
    rs0 += __shfl_xor_sync(0xFFFFFFFFu, rs0, 1);
    rs0 += __shfl_xor_sync(0xFFFFFFFFu, rs0, 2);
    rs1 += __shfl_xor_sync(0xFFFFFFFFu, rs1, 1);
    rs1 += __shfl_xor_sync(0xFFFFFFFFu, rs1, 2);
    if (tig == 0) {
        sInv[r0]     = 1.f / rs0;
        sInv[r0 + 8] = 1.f / rs1;
    }
    __syncthreads();

    // ---- normalize att in place (fp32, streaming hints) ----
    for (int r = 0; r < 128; ++r) {
        float iv = sInv[r];
        float* row = attg + (size_t)r * Ss + tid * 8;
        float4 a = ldcs_f4(row);
        float4 c = ldcs_f4(row + 4);
        a.x *= iv; a.y *= iv; a.z *= iv; a.w *= iv;
        c.x *= iv; c.y *= iv; c.z *= iv; c.w *= iv;
        stcs_f4(row, a);
        stcs_f4(row + 4, c);
    }
}

extern "C" void kernel_launch(void* const* d_in, const int* in_sizes, int n_in,
                              void* d_out, int out_size)
{
    const float* q = (const float*)d_in[0];
    const float* k = (const float*)d_in[1];
    const float* v = (const float*)d_in[2];
    const int* masks = (const int*)d_in[3];
    float* out = (float*)d_out;

    prep_kernel<<<40960, 256>>>(masks, k, v);

    cudaFuncSetAttribute(sdpa_main_kernel,
                         cudaFuncAttributeMaxDynamicSharedMemorySize, SMEM_TOTAL);

    dim3 grid(Ss / 128, BH);   // (16, 32)
    sdpa_main_kernel<<<grid, 256, SMEM_TOTAL>>>(q, out);
}